// round 7
// baseline (speedup 1.0000x reference)
#include <cuda_runtime.h>
#include <math.h>

#define BDIM 16
#define SDIM 2048
#define IDIM 1024
#define HDIM 1024
#define NBLK 128   // GRU persistent blocks (1 per SM, 8 hidden cols each)

// Scratch (static __device__ — runtime allocation is forbidden)
__device__ float g_gi[(size_t)BDIM * SDIM * 3 * HDIM];   // [B,S,3H]
__device__ float g_rnn[(size_t)BDIM * SDIM * HDIM];      // [B,S,H]
__device__ float g_hT[2 * HDIM * BDIM];                  // transposed h, double-buffered [buf][k][b]
__device__ unsigned g_flags[NBLK * 8];                   // per-block step flags, 32B stride

// ---------------------------------------------------------------------------
// f32x2 packed-math helpers (sm_100+)
// ---------------------------------------------------------------------------
__device__ __forceinline__ unsigned long long dup2(float x) {
    unsigned long long r;
    asm("mov.b64 %0, {%1, %1};" : "=l"(r) : "f"(x));
    return r;
}
__device__ __forceinline__ float2 unpack2(unsigned long long v) {
    float2 f;
    asm("mov.b64 {%0, %1}, %2;" : "=f"(f.x), "=f"(f.y) : "l"(v));
    return f;
}
#define FMA2(d, a, b) asm("fma.rn.f32x2 %0, %1, %2, %0;" : "+l"(d) : "l"(a), "l"(b))
#define ADD2(d, a)    asm("add.rn.f32x2 %0, %0, %1;"     : "+l"(d) : "l"(a))

__device__ __forceinline__ unsigned long long shfl_xor_ull(unsigned long long v, int m) {
    unsigned lo, hi;
    asm("mov.b64 {%0, %1}, %2;" : "=r"(lo), "=r"(hi) : "l"(v));
    lo = __shfl_xor_sync(0xFFFFFFFFu, lo, m);
    hi = __shfl_xor_sync(0xFFFFFFFFu, hi, m);
    unsigned long long r;
    asm("mov.b64 %0, {%1, %2};" : "=l"(r) : "r"(lo), "r"(hi));
    return r;
}

// release/acquire flag ops
__device__ __forceinline__ void st_rel(unsigned* p, unsigned v) {
    asm volatile("st.release.gpu.global.b32 [%0], %1;" :: "l"(p), "r"(v) : "memory");
}
__device__ __forceinline__ unsigned ld_acq(const unsigned* p) {
    unsigned v;
    asm volatile("ld.acquire.gpu.global.b32 %0, [%1];" : "=r"(v) : "l"(p) : "memory");
    return v;
}

// cp.async.cg: 16B global->shared, L2-only (coherent with peer SMs' released stores)
#define CP_ASYNC16(dst_u32, src_ptr) \
    asm volatile("cp.async.cg.shared.global [%0], [%1], 16;" :: "r"(dst_u32), "l"(src_ptr))
#define CP_COMMIT() asm volatile("cp.async.commit_group;")
#define CP_WAIT0()  asm volatile("cp.async.wait_group 0;")

// ---------------------------------------------------------------------------
// NT SGEMM (f32x2): C[m,n] = sum_k A[m,k] * W[n,k] + bias[n]
// 128x128 tile, BK=16, 256 threads, 8x8 per thread (as 8x4 f32x2).
// ---------------------------------------------------------------------------
__global__ void __launch_bounds__(256) sgemm_nt(
    const float* __restrict__ A, const float* __restrict__ W,
    const float* __restrict__ bias, float* __restrict__ C,
    int M, int N, int K)
{
    __shared__ float As[16][128];
    __shared__ float Bs[16][128];

    const int tid = threadIdx.x;
    const int bm = blockIdx.y * 128;
    const int bn = blockIdx.x * 128;
    const int tx = tid & 15;
    const int ty = tid >> 4;

    unsigned long long acc[8][4];
#pragma unroll
    for (int i = 0; i < 8; i++)
#pragma unroll
        for (int j = 0; j < 4; j++) acc[i][j] = 0ull;

    for (int k0 = 0; k0 < K; k0 += 16) {
#pragma unroll
        for (int i = 0; i < 2; i++) {
            int e = tid + i * 256;
            int row = e >> 2;
            int quad = e & 3;
            float4 av = *(const float4*)(&A[(size_t)(bm + row) * K + k0 + quad * 4]);
            float4 wv = *(const float4*)(&W[(size_t)(bn + row) * K + k0 + quad * 4]);
            As[quad * 4 + 0][row] = av.x;
            As[quad * 4 + 1][row] = av.y;
            As[quad * 4 + 2][row] = av.z;
            As[quad * 4 + 3][row] = av.w;
            Bs[quad * 4 + 0][row] = wv.x;
            Bs[quad * 4 + 1][row] = wv.y;
            Bs[quad * 4 + 2][row] = wv.z;
            Bs[quad * 4 + 3][row] = wv.w;
        }
        __syncthreads();

#pragma unroll
        for (int k = 0; k < 16; k++) {
            float a8[8];
            *(float4*)&a8[0] = *(const float4*)&As[k][ty * 8];
            *(float4*)&a8[4] = *(const float4*)&As[k][ty * 8 + 4];
            unsigned long long bp[4];
            {
                ulonglong2 t0 = *(const ulonglong2*)&Bs[k][tx * 8];
                ulonglong2 t1 = *(const ulonglong2*)&Bs[k][tx * 8 + 4];
                bp[0] = t0.x; bp[1] = t0.y; bp[2] = t1.x; bp[3] = t1.y;
            }
            unsigned long long ad[8];
#pragma unroll
            for (int i = 0; i < 8; i++) ad[i] = dup2(a8[i]);
#pragma unroll
            for (int i = 0; i < 8; i++)
#pragma unroll
                for (int j = 0; j < 4; j++)
                    FMA2(acc[i][j], ad[i], bp[j]);
        }
        __syncthreads();
    }

#pragma unroll
    for (int i = 0; i < 8; i++) {
        size_t row = (size_t)(bm + ty * 8 + i);
#pragma unroll
        for (int j = 0; j < 4; j++) {
            float2 f = unpack2(acc[i][j]);
            int n = bn + tx * 8 + 2 * j;
            float2 v;
            v.x = f.x + bias[n];
            v.y = f.y + bias[n + 1];
            *(float2*)&C[row * N + n] = v;
        }
    }
}

// ---------------------------------------------------------------------------
// Persistent GRU v2. 128 blocks x 256 threads; block owns 8 hidden cols.
// Warp w owns k-slice [128w, 128w+128); lane = (j = lane&7, ks4 = lane>>3).
// w_hh held in REGISTERS (3x32 floats per thread, loaded once).
// h_s: [1024 rows][20 floats], rows k-interleaved within each 128-chunk:
//   srow(k) = (k & ~127) | ((k&31)<<2) | ((k>>5)&3)
// so the 4 concurrently-read rows are adjacent (conflict-free at HROW=20).
// Reduction: shfl xor 8/16 over ks4-equivalents -> 12KB dump -> 8-way sums.
// Sync: per-warp flag polling of the 16 producer blocks of its k-slice.
// ---------------------------------------------------------------------------
#define HROW 20
#define SM_H   (1024 * HROW)               // floats (80KB)
#define SM_RED (8 * 8 * 3 * 8)             // ull entries (12.3KB)

__global__ void reset_flags_kernel()
{
    g_flags[threadIdx.x * 8] = 0u;
}

__global__ void __launch_bounds__(256, 1) gru_persistent(
    const float* __restrict__ gi, const float* __restrict__ w_hh,
    const float* __restrict__ b_hh, float* __restrict__ rnn,
    float* __restrict__ hT)
{
    extern __shared__ float sm[];
    float* h_s = sm;
    unsigned long long* red_s = (unsigned long long*)(sm + SM_H);
    const unsigned hs_u32 = (unsigned)__cvta_generic_to_shared(h_s);

    const int tid = threadIdx.x;
    const int bx = blockIdx.x;
    const int w = tid >> 5;
    const int lane = tid & 31;
    const int j = lane & 7;
    const int ks4 = lane >> 3;
    const int kbase = (w << 7) + (ks4 << 5);

    // --- load own w_hh slice into REGISTERS (once, reused 2048 steps) ---
    float wreg[3][32];
#pragma unroll
    for (int g = 0; g < 3; g++)
#pragma unroll
        for (int i4 = 0; i4 < 8; i4++) {
            float4 v = *(const float4*)(w_hh +
                ((size_t)(g * 1024 + bx * 8 + j)) * 1024 + kbase + (i4 << 2));
            wreg[g][i4 * 4 + 0] = v.x;
            wreg[g][i4 * 4 + 1] = v.y;
            wreg[g][i4 * 4 + 2] = v.z;
            wreg[g][i4 * 4 + 3] = v.w;
        }

    // combine-thread constants (warps 0-3)
    const int jl_c = tid >> 4, b_c = tid & 15;
    const int col_c = bx * 8 + jl_c;
    // permuted h_s row of col_c (for hprev)
    const int srow_c = (col_c & ~127) | ((col_c & 31) << 2) | ((col_c >> 5) & 3);
    float bh0 = 0.f, bh1 = 0.f, bh2 = 0.f;
    if (tid < 128) {
        bh0 = b_hh[col_c];
        bh1 = b_hh[1024 + col_c];
        bh2 = b_hh[2048 + col_c];
    }

    // pre-zero h_s (t=0 reads zeros)
    {
        float4 z4 = make_float4(0.f, 0.f, 0.f, 0.f);
        for (int r = tid; r < SM_H / 4; r += 256)
            ((float4*)h_s)[r] = z4;
    }
    __syncthreads();

    for (int t = 0; t < SDIM; t++) {
        // --- prefetch gi early (DRAM latency hidden under staging+mainloop) ---
        float gir = 0.f, giz = 0.f, gin = 0.f;
        if (tid < 128) {
            const size_t gb = ((size_t)b_c * SDIM + t) * 3072 + col_c;
            gir = __ldg(gi + gb);
            giz = __ldg(gi + gb + 1024);
            gin = __ldg(gi + gb + 2048);
        }

        // --- per-warp: wait for this k-slice's 16 producers, stage 8KB ---
        if (t > 0) {
            if (lane < 16) {
                const unsigned* fp = &g_flags[((w << 4) + lane) * 8];
                while (ld_acq(fp) < (unsigned)t) {}
            }
            __syncwarp();
            const float* src = hT + ((t - 1) & 1) * (HDIM * BDIM) + ((w << 7) << 4);
#pragma unroll
            for (int n = 0; n < 16; n++) {
                int r = lane + (n << 5);          // 0..511 (16B chunks)
                int kl = r >> 2, q = r & 3;
                int srl = ((kl & 31) << 2) | (kl >> 5);
                unsigned dst = hs_u32 +
                    (unsigned)((((w << 7) + srl) * HROW + (q << 2)) * 4);
                CP_ASYNC16(dst, src + (r << 2));
            }
            CP_COMMIT();
            CP_WAIT0();
            __syncwarp();
        }

        // --- mainloop: 32 k-iters, 24 FMA2/iter, w from registers ---
        unsigned long long acc[3][8];
#pragma unroll
        for (int g = 0; g < 3; g++)
#pragma unroll
            for (int p = 0; p < 8; p++) acc[g][p] = 0ull;

#pragma unroll
        for (int i = 0; i < 32; i++) {
            const float* hrow = h_s + ((w << 7) + (i << 2) + ks4) * HROW;
            unsigned long long hp[8];
            {
                ulonglong2 u0 = *(const ulonglong2*)(hrow);
                ulonglong2 u1 = *(const ulonglong2*)(hrow + 4);
                ulonglong2 u2 = *(const ulonglong2*)(hrow + 8);
                ulonglong2 u3 = *(const ulonglong2*)(hrow + 12);
                hp[0] = u0.x; hp[1] = u0.y; hp[2] = u1.x; hp[3] = u1.y;
                hp[4] = u2.x; hp[5] = u2.y; hp[6] = u3.x; hp[7] = u3.y;
            }
#pragma unroll
            for (int g = 0; g < 3; g++) {
                unsigned long long wd = dup2(wreg[g][i]);
#pragma unroll
                for (int p = 0; p < 8; p++) FMA2(acc[g][p], wd, hp[p]);
            }
        }

        // --- intra-warp reduce over ks4 (butterfly xor 8, xor 16) ---
#pragma unroll
        for (int g = 0; g < 3; g++)
#pragma unroll
            for (int p = 0; p < 8; p++) {
                unsigned long long s8 = shfl_xor_ull(acc[g][p], 8);
                ADD2(acc[g][p], s8);
                unsigned long long s16 = shfl_xor_ull(acc[g][p], 16);
                ADD2(acc[g][p], s16);
            }

        // --- cross-warp dump (lanes with ks4==0 hold full warp partials) ---
        __syncthreads();   // red_s free (prev combine done via post-combine sync)
        if (lane < 8) {
            unsigned long long* rp = red_s + ((w * 8 + lane) * 3) * 8;
#pragma unroll
            for (int g = 0; g < 3; g++)
#pragma unroll
                for (int p = 0; p < 8; p++)
                    rp[g * 8 + p] = acc[g][p];
        }
        __syncthreads();

        // --- combine: sum 8 warp-partials, activations, write ---
        if (tid < 128) {
            const float* rf = (const float*)red_s;
            const int base = jl_c * 48 + b_c;   // + wq*384 + g*16
            float ar = 0.f, az = 0.f, an = 0.f;
#pragma unroll
            for (int wq = 0; wq < 8; wq++) {
                ar += rf[wq * 384 + base];
                az += rf[wq * 384 + base + 16];
                an += rf[wq * 384 + base + 32];
            }
            float hprev = h_s[srow_c * HROW + b_c];

            float r = 1.f / (1.f + expf(-(gir + ar + bh0)));
            float z = 1.f / (1.f + expf(-(giz + az + bh1)));
            float n = tanhf(gin + r * (an + bh2));
            float hnew = (1.f - z) * n + z * hprev;

            rnn[((size_t)b_c * SDIM + t) * HDIM + col_c] = hnew;
            hT[(t & 1) * (HDIM * BDIM) + col_c * BDIM + b_c] = hnew;
        }

        // --- publish ---
        __syncthreads();
        if (tid == 0) st_rel(&g_flags[bx * 8], (unsigned)(t + 1));
    }
}

// ---------------------------------------------------------------------------
// hidden = rnn[:, S-1, :]; attn = ones (softmax over a size-1 axis).
// d_out layout: [output B*S*I][hidden B*H][attn B*S]
// ---------------------------------------------------------------------------
__global__ void finalize_kernel(const float* __restrict__ rnn, float* __restrict__ out)
{
    const size_t OUT_ELEMS = (size_t)BDIM * SDIM * IDIM;
    int i = blockIdx.x * blockDim.x + threadIdx.x;
    if (i < BDIM * HDIM) {
        int b = i >> 10, h = i & 1023;
        out[OUT_ELEMS + i] = rnn[((size_t)b * SDIM + (SDIM - 1)) * HDIM + h];
    }
    if (i < BDIM * SDIM) {
        out[OUT_ELEMS + BDIM * HDIM + i] = 1.0f;
    }
}

extern "C" void kernel_launch(void* const* d_in, const int* in_sizes, int n_in,
                              void* d_out, int out_size)
{
    const float* x    = (const float*)d_in[0];
    // d_in[1..4] = attn MLP -> algebraically dead (softmax over size-1 axis == 1)
    const float* w_ih = (const float*)d_in[5];
    const float* w_hh = (const float*)d_in[6];
    const float* b_ih = (const float*)d_in[7];
    const float* b_hh = (const float*)d_in[8];
    const float* fc_w = (const float*)d_in[9];
    const float* fc_b = (const float*)d_in[10];
    float* out = (float*)d_out;

    float *gi = nullptr, *rnn = nullptr, *hT = nullptr;
    cudaGetSymbolAddress((void**)&gi, g_gi);
    cudaGetSymbolAddress((void**)&rnn, g_rnn);
    cudaGetSymbolAddress((void**)&hT, g_hT);

    const int smemB = SM_H * (int)sizeof(float) + SM_RED * (int)sizeof(unsigned long long);
    static bool attr_done = false;
    if (!attr_done) {
        cudaFuncSetAttribute(gru_persistent, cudaFuncAttributeMaxDynamicSharedMemorySize, smemB);
        attr_done = true;
    }

    // gi = x @ w_ih^T + b_ih   (M=32768, N=3072, K=1024)
    {
        dim3 grid(3 * HDIM / 128, BDIM * SDIM / 128);
        sgemm_nt<<<grid, 256>>>(x, w_ih, b_ih, gi, BDIM * SDIM, 3 * HDIM, IDIM);
    }

    // reset per-block flags (stream-ordered before the persistent kernel)
    reset_flags_kernel<<<1, NBLK>>>();

    // GRU: one persistent kernel, 2048 steps, distributed flag sync
    gru_persistent<<<NBLK, 256, smemB>>>(gi, w_hh, b_hh, rnn, hT);

    // output = rnn_out @ fc_w^T + fc_b   (M=32768, N=1024, K=1024)
    {
        dim3 grid(IDIM / 128, BDIM * SDIM / 128);
        sgemm_nt<<<grid, 256>>>(rnn, fc_w, fc_b, out, BDIM * SDIM, IDIM, HDIM);
    }

    finalize_kernel<<<192, 256>>>(rnn, out);
}

// round 9
// speedup vs baseline: 1.1941x; 1.1941x over previous
#include <cuda_runtime.h>
#include <math.h>

#define BDIM 16
#define SDIM 2048
#define IDIM 1024
#define HDIM 1024
#define NBLK 128   // GRU persistent blocks (1 per SM, 8 hidden cols each)

// Scratch (static __device__ — runtime allocation is forbidden)
__device__ float g_gi[(size_t)BDIM * SDIM * 3 * HDIM];   // [B,S,3H]
__device__ float g_rnn[(size_t)BDIM * SDIM * HDIM];      // [B,S,H]
__device__ float g_hT[2 * HDIM * BDIM];                  // transposed h, double-buffered [buf][k][b]
__device__ unsigned g_flags[NBLK * 8];                   // per-block step flags, 32B stride

// ---------------------------------------------------------------------------
// f32x2 packed-math helpers (sm_100+)
// ---------------------------------------------------------------------------
__device__ __forceinline__ unsigned long long dup2(float x) {
    unsigned long long r;
    asm("mov.b64 %0, {%1, %1};" : "=l"(r) : "f"(x));
    return r;
}
__device__ __forceinline__ float2 unpack2(unsigned long long v) {
    float2 f;
    asm("mov.b64 {%0, %1}, %2;" : "=f"(f.x), "=f"(f.y) : "l"(v));
    return f;
}
#define FMA2(d, a, b) asm("fma.rn.f32x2 %0, %1, %2, %0;" : "+l"(d) : "l"(a), "l"(b))
#define ADD2(d, a)    asm("add.rn.f32x2 %0, %0, %1;"     : "+l"(d) : "l"(a))

// release/acquire flag ops (strong ops bypass L1; L2 is the coherence point)
__device__ __forceinline__ void st_rel(unsigned* p, unsigned v) {
    asm volatile("st.release.gpu.global.b32 [%0], %1;" :: "l"(p), "r"(v) : "memory");
}
__device__ __forceinline__ unsigned ld_acq(const unsigned* p) {
    unsigned v;
    asm volatile("ld.acquire.gpu.global.b32 %0, [%1];" : "=r"(v) : "l"(p) : "memory");
    return v;
}

// ---------------------------------------------------------------------------
// NT SGEMM (f32x2): C[m,n] = sum_k A[m,k] * W[n,k] + bias[n]
// 128x128 tile, BK=16, 256 threads, 8x8 per thread (as 8x4 f32x2).
// ---------------------------------------------------------------------------
__global__ void __launch_bounds__(256) sgemm_nt(
    const float* __restrict__ A, const float* __restrict__ W,
    const float* __restrict__ bias, float* __restrict__ C,
    int M, int N, int K)
{
    __shared__ float As[16][128];
    __shared__ float Bs[16][128];

    const int tid = threadIdx.x;
    const int bm = blockIdx.y * 128;
    const int bn = blockIdx.x * 128;
    const int tx = tid & 15;
    const int ty = tid >> 4;

    unsigned long long acc[8][4];
#pragma unroll
    for (int i = 0; i < 8; i++)
#pragma unroll
        for (int j = 0; j < 4; j++) acc[i][j] = 0ull;

    for (int k0 = 0; k0 < K; k0 += 16) {
#pragma unroll
        for (int i = 0; i < 2; i++) {
            int e = tid + i * 256;
            int row = e >> 2;
            int quad = e & 3;
            float4 av = *(const float4*)(&A[(size_t)(bm + row) * K + k0 + quad * 4]);
            float4 wv = *(const float4*)(&W[(size_t)(bn + row) * K + k0 + quad * 4]);
            As[quad * 4 + 0][row] = av.x;
            As[quad * 4 + 1][row] = av.y;
            As[quad * 4 + 2][row] = av.z;
            As[quad * 4 + 3][row] = av.w;
            Bs[quad * 4 + 0][row] = wv.x;
            Bs[quad * 4 + 1][row] = wv.y;
            Bs[quad * 4 + 2][row] = wv.z;
            Bs[quad * 4 + 3][row] = wv.w;
        }
        __syncthreads();

#pragma unroll
        for (int k = 0; k < 16; k++) {
            float a8[8];
            *(float4*)&a8[0] = *(const float4*)&As[k][ty * 8];
            *(float4*)&a8[4] = *(const float4*)&As[k][ty * 8 + 4];
            unsigned long long bp[4];
            {
                ulonglong2 t0 = *(const ulonglong2*)&Bs[k][tx * 8];
                ulonglong2 t1 = *(const ulonglong2*)&Bs[k][tx * 8 + 4];
                bp[0] = t0.x; bp[1] = t0.y; bp[2] = t1.x; bp[3] = t1.y;
            }
            unsigned long long ad[8];
#pragma unroll
            for (int i = 0; i < 8; i++) ad[i] = dup2(a8[i]);
#pragma unroll
            for (int i = 0; i < 8; i++)
#pragma unroll
                for (int j = 0; j < 4; j++)
                    FMA2(acc[i][j], ad[i], bp[j]);
        }
        __syncthreads();
    }

#pragma unroll
    for (int i = 0; i < 8; i++) {
        size_t row = (size_t)(bm + ty * 8 + i);
#pragma unroll
        for (int j = 0; j < 4; j++) {
            float2 f = unpack2(acc[i][j]);
            int n = bn + tx * 8 + 2 * j;
            float2 v;
            v.x = f.x + bias[n];
            v.y = f.y + bias[n + 1];
            *(float2*)&C[row * N + n] = v;
        }
    }
}

// ---------------------------------------------------------------------------
// Persistent GRU (R4 structure; barrier = distributed flags, hT reads = __ldcg).
// 128 blocks x 256 threads; block owns 8 hidden cols.
// SMEM: w_s[24][1024] resident, h_s[1024][20] staged per step ([k][b] layout,
// reused as reduction dump), red_s[2*96] f32x2.
// ---------------------------------------------------------------------------
#define HROW 20            // floats per h_s row (16 used + 4 pad -> conflict-free LDS.128)
#define SM_W   (24 * 1024)                 // floats
#define SM_H   (1024 * HROW)               // floats
#define SM_RED 192                         // ull (f32x2) entries

__global__ void reset_flags_kernel()
{
    g_flags[threadIdx.x * 8] = 0u;
}

__global__ void __launch_bounds__(256, 1) gru_persistent(
    const float* __restrict__ gi, const float* __restrict__ w_hh,
    const float* __restrict__ b_hh, float* __restrict__ rnn,
    float* __restrict__ hT)
{
    extern __shared__ float sm[];
    float* w_s = sm;
    float* h_s = sm + SM_W;
    unsigned long long* red_s = (unsigned long long*)(sm + SM_W + SM_H);

    const int tid = threadIdx.x;
    const int bx = blockIdx.x;
    const int cg = tid >> 6;      // 0..3 column group
    const int ks = tid & 63;      // k slice

    // --- load own w_hh rows into smem (once) ---
    for (int idx = tid; idx < 24 * 256; idx += 256) {
        int lr = idx >> 8;
        int k4 = idx & 255;
        int g = lr >> 3, jl = lr & 7;
        float4 v = *(const float4*)(w_hh + ((size_t)(g * 1024 + bx * 8 + jl)) * 1024 + k4 * 4);
        *(float4*)(w_s + lr * 1024 + k4 * 4) = v;
    }

    // combine-thread constants
    const int jl_c = tid >> 4, b_c = tid & 15;
    const int col_c = bx * 8 + jl_c;
    float bh0 = 0.f, bh1 = 0.f, bh2 = 0.f;
    if (tid < 128) {
        bh0 = b_hh[col_c];
        bh1 = b_hh[1024 + col_c];
        bh2 = b_hh[2048 + col_c];
    }

    // per-thread w pointers (invariant across steps): c = jsub*3 + g
    const int j0 = cg * 2;
    const float* wc[6];
#pragma unroll
    for (int jsub = 0; jsub < 2; jsub++)
#pragma unroll
        for (int g = 0; g < 3; g++)
            wc[jsub * 3 + g] = w_s + (g * 8 + j0 + jsub) * 1024 + ks;

    __syncthreads();

    for (int t = 0; t < SDIM; t++) {
        // --- stage h_{t-1} into h_s[k][b] (L2-coherent loads: __ldcg) ---
        if (t == 0) {
            float4 z4 = make_float4(0.f, 0.f, 0.f, 0.f);
            for (int r = tid; r < SM_H / 4; r += 256)
                ((float4*)h_s)[r] = z4;
        } else {
            const float* src = hT + ((t - 1) & 1) * (HDIM * BDIM);
            for (int r = tid; r < 4096; r += 256) {
                float4 v = __ldcg((const float4*)(src + r * 4));
                int k = r >> 2, b4 = r & 3;
                *(float4*)(h_s + k * HROW + b4 * 4) = v;
            }
        }
        __syncthreads();

        // --- prefetch gi + hprev (hidden under the mainloop) ---
        float gir = 0.f, giz = 0.f, gin = 0.f, hprev = 0.f;
        if (tid < 128) {
            const size_t gb = ((size_t)b_c * SDIM + t) * 3072 + col_c;
            gir = __ldg(gi + gb);
            giz = __ldg(gi + gb + 1024);
            gin = __ldg(gi + gb + 2048);
            hprev = h_s[col_c * HROW + b_c];
        }

        // --- mainloop: 6 cols x 8 f32x2 x 16 k-iters ---
        unsigned long long acc[6][8];
#pragma unroll
        for (int c = 0; c < 6; c++)
#pragma unroll
            for (int p = 0; p < 8; p++) acc[c][p] = 0ull;

#pragma unroll 4
        for (int i = 0; i < 16; i++) {
            const int k = ks + (i << 6);
            const float* hrow = h_s + k * HROW;
            unsigned long long hp[8];
            {
                ulonglong2 u0 = *(const ulonglong2*)(hrow);
                ulonglong2 u1 = *(const ulonglong2*)(hrow + 4);
                ulonglong2 u2 = *(const ulonglong2*)(hrow + 8);
                ulonglong2 u3 = *(const ulonglong2*)(hrow + 12);
                hp[0] = u0.x; hp[1] = u0.y; hp[2] = u1.x; hp[3] = u1.y;
                hp[4] = u2.x; hp[5] = u2.y; hp[6] = u3.x; hp[7] = u3.y;
            }
#pragma unroll
            for (int c = 0; c < 6; c++) {
                unsigned long long wd = dup2(wc[c][i << 6]);
#pragma unroll
                for (int p = 0; p < 8; p++) FMA2(acc[c][p], wd, hp[p]);
            }
        }

        // --- 64-way k reduction in two halves (dump reuses h_s) ---
        unsigned long long* dmp = (unsigned long long*)h_s;
#pragma unroll
        for (int hh = 0; hh < 2; hh++) {
            __syncthreads();   // h_s / previous dump fully consumed
#pragma unroll
            for (int g = 0; g < 3; g++)
#pragma unroll
                for (int p = 0; p < 8; p++)
                    dmp[tid * 25 + g * 8 + p] = acc[hh * 3 + g][p];
            __syncthreads();
            if (tid < 96) {
                int cgo = tid / 24, s = tid % 24;
                unsigned long long sum = dmp[(cgo * 64) * 25 + s];
#pragma unroll 8
                for (int q = 1; q < 64; q++)
                    ADD2(sum, dmp[(cgo * 64 + q) * 25 + s]);
                red_s[hh * 96 + cgo * 24 + s] = sum;
            }
        }
        __syncthreads();

        // --- combine + activations + write ---
        if (tid < 128) {
            int cgc = jl_c >> 1, hh = jl_c & 1, p = b_c >> 1, lane = b_c & 1;
            const float* rf = (const float*)red_s;
            int base = (hh * 96 + cgc * 24) * 2 + p * 2 + lane;
            float ar = rf[base];
            float az = rf[base + 16];   // (g=1)*8*2
            float an = rf[base + 32];   // (g=2)*8*2

            float r = 1.f / (1.f + expf(-(gir + ar + bh0)));
            float z = 1.f / (1.f + expf(-(giz + az + bh1)));
            float n = tanhf(gin + r * (an + bh2));
            float hnew = (1.f - z) * n + z * hprev;

            rnn[((size_t)b_c * SDIM + t) * HDIM + col_c] = hnew;
            hT[(t & 1) * (HDIM * BDIM) + col_c * BDIM + b_c] = hnew;
        }

        // --- distributed flag barrier (replaces central-atomic gsync) ---
        __syncthreads();                       // hT writes of this block done
        if (tid == 0) st_rel(&g_flags[bx * 8], (unsigned)(t + 1));
        if (tid < NBLK) {
            const unsigned* fp = &g_flags[tid * 8];
            while (ld_acq(fp) <= (unsigned)t) {}
        }
        __syncthreads();                       // all 128 blocks published h_t
    }
}

// ---------------------------------------------------------------------------
// hidden = rnn[:, S-1, :]; attn = ones (softmax over a size-1 axis).
// d_out layout: [output B*S*I][hidden B*H][attn B*S]
// ---------------------------------------------------------------------------
__global__ void finalize_kernel(const float* __restrict__ rnn, float* __restrict__ out)
{
    const size_t OUT_ELEMS = (size_t)BDIM * SDIM * IDIM;
    int i = blockIdx.x * blockDim.x + threadIdx.x;
    if (i < BDIM * HDIM) {
        int b = i >> 10, h = i & 1023;
        out[OUT_ELEMS + i] = rnn[((size_t)b * SDIM + (SDIM - 1)) * HDIM + h];
    }
    if (i < BDIM * SDIM) {
        out[OUT_ELEMS + BDIM * HDIM + i] = 1.0f;
    }
}

extern "C" void kernel_launch(void* const* d_in, const int* in_sizes, int n_in,
                              void* d_out, int out_size)
{
    const float* x    = (const float*)d_in[0];
    // d_in[1..4] = attn MLP -> algebraically dead (softmax over size-1 axis == 1)
    const float* w_ih = (const float*)d_in[5];
    const float* w_hh = (const float*)d_in[6];
    const float* b_ih = (const float*)d_in[7];
    const float* b_hh = (const float*)d_in[8];
    const float* fc_w = (const float*)d_in[9];
    const float* fc_b = (const float*)d_in[10];
    float* out = (float*)d_out;

    float *gi = nullptr, *rnn = nullptr, *hT = nullptr;
    cudaGetSymbolAddress((void**)&gi, g_gi);
    cudaGetSymbolAddress((void**)&rnn, g_rnn);
    cudaGetSymbolAddress((void**)&hT, g_hT);

    const int smemB = (SM_W + SM_H) * (int)sizeof(float) + SM_RED * (int)sizeof(unsigned long long);
    static bool attr_done = false;
    if (!attr_done) {
        cudaFuncSetAttribute(gru_persistent, cudaFuncAttributeMaxDynamicSharedMemorySize, smemB);
        attr_done = true;
    }

    // gi = x @ w_ih^T + b_ih   (M=32768, N=3072, K=1024)
    {
        dim3 grid(3 * HDIM / 128, BDIM * SDIM / 128);
        sgemm_nt<<<grid, 256>>>(x, w_ih, b_ih, gi, BDIM * SDIM, 3 * HDIM, IDIM);
    }

    // reset per-block flags (stream-ordered before the persistent kernel)
    reset_flags_kernel<<<1, NBLK>>>();

    // GRU: one persistent kernel, 2048 steps, distributed flag barrier
    gru_persistent<<<NBLK, 256, smemB>>>(gi, w_hh, b_hh, rnn, hT);

    // output = rnn_out @ fc_w^T + fc_b   (M=32768, N=1024, K=1024)
    {
        dim3 grid(IDIM / 128, BDIM * SDIM / 128);
        sgemm_nt<<<grid, 256>>>(rnn, fc_w, fc_b, out, BDIM * SDIM, IDIM, HDIM);
    }

    finalize_kernel<<<192, 256>>>(rnn, out);
}

// round 10
// speedup vs baseline: 1.8919x; 1.5844x over previous
#include <cuda_runtime.h>
#include <math.h>

#define BDIM 16
#define SDIM 2048
#define IDIM 1024
#define HDIM 1024
#define NBLK 128   // GRU persistent blocks (1 per SM, 8 hidden cols each)

// Scratch (static __device__ — runtime allocation is forbidden)
__device__ float g_gi[(size_t)BDIM * SDIM * 3 * HDIM];   // [B,S,3H]
__device__ float g_rnn[(size_t)BDIM * SDIM * HDIM];      // [B,S,H]
__device__ float g_hT[2 * HDIM * BDIM];                  // transposed h, double-buffered [buf][k][b]

// two-level barrier state (monotonic counters; reset by kernel each launch)
__device__ unsigned g_gcount[16 * 32];                   // 16 group counters, 128B apart
__device__ unsigned g_count = 0;                         // root counter
__device__ volatile unsigned g_gen = 0;                  // release generation

// ---------------------------------------------------------------------------
// f32x2 packed-math helpers (sm_100+)
// ---------------------------------------------------------------------------
__device__ __forceinline__ unsigned long long dup2(float x) {
    unsigned long long r;
    asm("mov.b64 %0, {%1, %1};" : "=l"(r) : "f"(x));
    return r;
}
__device__ __forceinline__ float2 unpack2(unsigned long long v) {
    float2 f;
    asm("mov.b64 {%0, %1}, %2;" : "=f"(f.x), "=f"(f.y) : "l"(v));
    return f;
}
#define FMA2(d, a, b) asm("fma.rn.f32x2 %0, %1, %2, %0;" : "+l"(d) : "l"(a), "l"(b))
#define ADD2(d, a)    asm("add.rn.f32x2 %0, %0, %1;"     : "+l"(d) : "l"(a))

// ---------------------------------------------------------------------------
// NT SGEMM (f32x2): C[m,n] = sum_k A[m,k] * W[n,k] + bias[n]
// 128x128 tile, BK=16, 256 threads, 8x8 per thread (as 8x4 f32x2).
// ---------------------------------------------------------------------------
__global__ void __launch_bounds__(256) sgemm_nt(
    const float* __restrict__ A, const float* __restrict__ W,
    const float* __restrict__ bias, float* __restrict__ C,
    int M, int N, int K)
{
    __shared__ float As[16][128];
    __shared__ float Bs[16][128];

    const int tid = threadIdx.x;
    const int bm = blockIdx.y * 128;
    const int bn = blockIdx.x * 128;
    const int tx = tid & 15;
    const int ty = tid >> 4;

    unsigned long long acc[8][4];
#pragma unroll
    for (int i = 0; i < 8; i++)
#pragma unroll
        for (int j = 0; j < 4; j++) acc[i][j] = 0ull;

    for (int k0 = 0; k0 < K; k0 += 16) {
#pragma unroll
        for (int i = 0; i < 2; i++) {
            int e = tid + i * 256;
            int row = e >> 2;
            int quad = e & 3;
            float4 av = *(const float4*)(&A[(size_t)(bm + row) * K + k0 + quad * 4]);
            float4 wv = *(const float4*)(&W[(size_t)(bn + row) * K + k0 + quad * 4]);
            As[quad * 4 + 0][row] = av.x;
            As[quad * 4 + 1][row] = av.y;
            As[quad * 4 + 2][row] = av.z;
            As[quad * 4 + 3][row] = av.w;
            Bs[quad * 4 + 0][row] = wv.x;
            Bs[quad * 4 + 1][row] = wv.y;
            Bs[quad * 4 + 2][row] = wv.z;
            Bs[quad * 4 + 3][row] = wv.w;
        }
        __syncthreads();

#pragma unroll
        for (int k = 0; k < 16; k++) {
            float a8[8];
            *(float4*)&a8[0] = *(const float4*)&As[k][ty * 8];
            *(float4*)&a8[4] = *(const float4*)&As[k][ty * 8 + 4];
            unsigned long long bp[4];
            {
                ulonglong2 t0 = *(const ulonglong2*)&Bs[k][tx * 8];
                ulonglong2 t1 = *(const ulonglong2*)&Bs[k][tx * 8 + 4];
                bp[0] = t0.x; bp[1] = t0.y; bp[2] = t1.x; bp[3] = t1.y;
            }
            unsigned long long ad[8];
#pragma unroll
            for (int i = 0; i < 8; i++) ad[i] = dup2(a8[i]);
#pragma unroll
            for (int i = 0; i < 8; i++)
#pragma unroll
                for (int j = 0; j < 4; j++)
                    FMA2(acc[i][j], ad[i], bp[j]);
        }
        __syncthreads();
    }

#pragma unroll
    for (int i = 0; i < 8; i++) {
        size_t row = (size_t)(bm + ty * 8 + i);
#pragma unroll
        for (int j = 0; j < 4; j++) {
            float2 f = unpack2(acc[i][j]);
            int n = bn + tx * 8 + 2 * j;
            float2 v;
            v.x = f.x + bias[n];
            v.y = f.y + bias[n + 1];
            *(float2*)&C[row * N + n] = v;
        }
    }
}

// ---------------------------------------------------------------------------
// Persistent GRU (R4 structure; barrier = two-level atomic tree).
// 128 blocks x 256 threads; block owns 8 hidden cols.
// SMEM: w_s[24][1024] resident, h_s[1024][20] staged per step ([k][b] layout,
// reused as reduction dump), red_s[2*96] f32x2, red2[192] f32x2.
// ---------------------------------------------------------------------------
#define HROW 20            // floats per h_s row (16 used + 4 pad -> conflict-free LDS.128)
#define SM_W   (24 * 1024)                 // floats
#define SM_H   (1024 * HROW)               // floats
#define SM_RED 192                         // ull (f32x2) entries
#define SM_RED2 192                        // ull stage-1 partials

__global__ void reset_sync_kernel()
{
    if (threadIdx.x == 0) { g_count = 0u; g_gen = 0u; }
    if (threadIdx.x < 16) g_gcount[threadIdx.x * 32] = 0u;
}

__global__ void __launch_bounds__(256, 1) gru_persistent(
    const float* __restrict__ gi, const float* __restrict__ w_hh,
    const float* __restrict__ b_hh, float* __restrict__ rnn,
    float* __restrict__ hT)
{
    extern __shared__ float sm[];
    float* w_s = sm;
    float* h_s = sm + SM_W;
    unsigned long long* red_s = (unsigned long long*)(sm + SM_W + SM_H);
    unsigned long long* red2  = red_s + SM_RED;

    const int tid = threadIdx.x;
    const int bx = blockIdx.x;
    const int cg = tid >> 6;      // 0..3 column group
    const int ks = tid & 63;      // k slice

    // --- load own w_hh rows into smem (once) ---
    for (int idx = tid; idx < 24 * 256; idx += 256) {
        int lr = idx >> 8;
        int k4 = idx & 255;
        int g = lr >> 3, jl = lr & 7;
        float4 v = *(const float4*)(w_hh + ((size_t)(g * 1024 + bx * 8 + jl)) * 1024 + k4 * 4);
        *(float4*)(w_s + lr * 1024 + k4 * 4) = v;
    }

    // combine-thread constants
    const int jl_c = tid >> 4, b_c = tid & 15;
    const int col_c = bx * 8 + jl_c;
    float bh0 = 0.f, bh1 = 0.f, bh2 = 0.f;
    if (tid < 128) {
        bh0 = b_hh[col_c];
        bh1 = b_hh[1024 + col_c];
        bh2 = b_hh[2048 + col_c];
    }

    // per-thread w pointers (invariant across steps): c = jsub*3 + g
    const int j0 = cg * 2;
    const float* wc[6];
#pragma unroll
    for (int jsub = 0; jsub < 2; jsub++)
#pragma unroll
        for (int g = 0; g < 3; g++)
            wc[jsub * 3 + g] = w_s + (g * 8 + j0 + jsub) * 1024 + ks;

    __syncthreads();

    for (int t = 0; t < SDIM; t++) {
        // --- stage h_{t-1} into h_s[k][b] ---
        if (t == 0) {
            float4 z4 = make_float4(0.f, 0.f, 0.f, 0.f);
            for (int r = tid; r < SM_H / 4; r += 256)
                ((float4*)h_s)[r] = z4;
        } else {
            const float* src = hT + ((t - 1) & 1) * (HDIM * BDIM);
            for (int r = tid; r < 4096; r += 256) {
                float4 v = *(const float4*)(src + r * 4);
                int k = r >> 2, b4 = r & 3;
                *(float4*)(h_s + k * HROW + b4 * 4) = v;
            }
        }
        __syncthreads();

        // --- prefetch gi + hprev (hidden under the mainloop) ---
        float gir = 0.f, giz = 0.f, gin = 0.f, hprev = 0.f;
        if (tid < 128) {
            const size_t gb = ((size_t)b_c * SDIM + t) * 3072 + col_c;
            gir = __ldg(gi + gb);
            giz = __ldg(gi + gb + 1024);
            gin = __ldg(gi + gb + 2048);
            hprev = h_s[col_c * HROW + b_c];
        }

        // --- mainloop: 6 cols x 8 f32x2 x 16 k-iters ---
        unsigned long long acc[6][8];
#pragma unroll
        for (int c = 0; c < 6; c++)
#pragma unroll
            for (int p = 0; p < 8; p++) acc[c][p] = 0ull;

#pragma unroll 4
        for (int i = 0; i < 16; i++) {
            const int k = ks + (i << 6);
            const float* hrow = h_s + k * HROW;
            unsigned long long hp[8];
            {
                ulonglong2 u0 = *(const ulonglong2*)(hrow);
                ulonglong2 u1 = *(const ulonglong2*)(hrow + 4);
                ulonglong2 u2 = *(const ulonglong2*)(hrow + 8);
                ulonglong2 u3 = *(const ulonglong2*)(hrow + 12);
                hp[0] = u0.x; hp[1] = u0.y; hp[2] = u1.x; hp[3] = u1.y;
                hp[4] = u2.x; hp[5] = u2.y; hp[6] = u3.x; hp[7] = u3.y;
            }
#pragma unroll
            for (int c = 0; c < 6; c++) {
                unsigned long long wd = dup2(wc[c][i << 6]);
#pragma unroll
                for (int p = 0; p < 8; p++) FMA2(acc[c][p], wd, hp[p]);
            }
        }

        // --- 64-way k reduction in two halves (dump reuses h_s) ---
        // stage-1: 192 threads sum 32 q's; stage-2: 96 threads add pairs.
        unsigned long long* dmp = (unsigned long long*)h_s;
#pragma unroll
        for (int hh = 0; hh < 2; hh++) {
            __syncthreads();   // h_s / previous dump fully consumed
#pragma unroll
            for (int g = 0; g < 3; g++)
#pragma unroll
                for (int p = 0; p < 8; p++)
                    dmp[tid * 25 + g * 8 + p] = acc[hh * 3 + g][p];
            __syncthreads();
            if (tid < 192) {
                int id = tid >> 1, qh = tid & 1;
                int cgo = id / 24, s = id % 24;
                const unsigned long long* base = dmp + (size_t)(cgo * 64 + qh * 32) * 25 + s;
                unsigned long long sum = base[0];
#pragma unroll 8
                for (int q = 1; q < 32; q++)
                    ADD2(sum, base[q * 25]);
                red2[tid] = sum;
            }
            __syncthreads();
            if (tid < 96) {
                unsigned long long sum = red2[tid * 2];
                ADD2(sum, red2[tid * 2 + 1]);
                red_s[hh * 96 + tid] = sum;
            }
        }
        __syncthreads();

        // --- combine + activations + write ---
        if (tid < 128) {
            int cgc = jl_c >> 1, hh = jl_c & 1, p = b_c >> 1, lane = b_c & 1;
            const float* rf = (const float*)red_s;
            int base = (hh * 96 + cgc * 24) * 2 + p * 2 + lane;
            float ar = rf[base];
            float az = rf[base + 16];   // (g=1)*8*2
            float an = rf[base + 32];   // (g=2)*8*2

            float r = 1.f / (1.f + expf(-(gir + ar + bh0)));
            float z = 1.f / (1.f + expf(-(giz + az + bh1)));
            float n = tanhf(gin + r * (an + bh2));
            float hnew = (1.f - z) * n + z * hprev;

            rnn[((size_t)b_c * SDIM + t) * HDIM + col_c] = hnew;
            hT[(t & 1) * (HDIM * BDIM) + col_c * BDIM + b_c] = hnew;
        }

        // --- two-level chip barrier (monotonic counters, single releaser) ---
        __syncthreads();                  // this block's hT writes issued
        if (tid == 0) {
            __threadfence();              // hT visible before arrival
            unsigned arr = atomicAdd(&g_gcount[(bx & 15) * 32], 1u);
            if ((arr & 7u) == 7u) {       // last of 8 in group
                unsigned garr = atomicAdd(&g_count, 1u);
                if ((garr & 15u) == 15u) {  // last group
                    __threadfence();
                    g_gen = (unsigned)(t + 1);
                }
            }
            while (g_gen <= (unsigned)t) {}
            __threadfence();              // acquire: peers' hT now visible
        }
        __syncthreads();
    }
}

// ---------------------------------------------------------------------------
// hidden = rnn[:, S-1, :]; attn = ones (softmax over a size-1 axis).
// d_out layout: [output B*S*I][hidden B*H][attn B*S]
// ---------------------------------------------------------------------------
__global__ void finalize_kernel(const float* __restrict__ rnn, float* __restrict__ out)
{
    const size_t OUT_ELEMS = (size_t)BDIM * SDIM * IDIM;
    int i = blockIdx.x * blockDim.x + threadIdx.x;
    if (i < BDIM * HDIM) {
        int b = i >> 10, h = i & 1023;
        out[OUT_ELEMS + i] = rnn[((size_t)b * SDIM + (SDIM - 1)) * HDIM + h];
    }
    if (i < BDIM * SDIM) {
        out[OUT_ELEMS + BDIM * HDIM + i] = 1.0f;
    }
}

extern "C" void kernel_launch(void* const* d_in, const int* in_sizes, int n_in,
                              void* d_out, int out_size)
{
    const float* x    = (const float*)d_in[0];
    // d_in[1..4] = attn MLP -> algebraically dead (softmax over size-1 axis == 1)
    const float* w_ih = (const float*)d_in[5];
    const float* w_hh = (const float*)d_in[6];
    const float* b_ih = (const float*)d_in[7];
    const float* b_hh = (const float*)d_in[8];
    const float* fc_w = (const float*)d_in[9];
    const float* fc_b = (const float*)d_in[10];
    float* out = (float*)d_out;

    float *gi = nullptr, *rnn = nullptr, *hT = nullptr;
    cudaGetSymbolAddress((void**)&gi, g_gi);
    cudaGetSymbolAddress((void**)&rnn, g_rnn);
    cudaGetSymbolAddress((void**)&hT, g_hT);

    const int smemB = (SM_W + SM_H) * (int)sizeof(float)
                    + (SM_RED + SM_RED2) * (int)sizeof(unsigned long long);
    static bool attr_done = false;
    if (!attr_done) {
        cudaFuncSetAttribute(gru_persistent, cudaFuncAttributeMaxDynamicSharedMemorySize, smemB);
        attr_done = true;
    }

    // gi = x @ w_ih^T + b_ih   (M=32768, N=3072, K=1024)
    {
        dim3 grid(3 * HDIM / 128, BDIM * SDIM / 128);
        sgemm_nt<<<grid, 256>>>(x, w_ih, b_ih, gi, BDIM * SDIM, 3 * HDIM, IDIM);
    }

    // reset barrier counters (stream-ordered before the persistent kernel)
    reset_sync_kernel<<<1, 32>>>();

    // GRU: one persistent kernel, 2048 steps, two-level atomic barrier
    gru_persistent<<<NBLK, 256, smemB>>>(gi, w_hh, b_hh, rnn, hT);

    // output = rnn_out @ fc_w^T + fc_b   (M=32768, N=1024, K=1024)
    {
        dim3 grid(IDIM / 128, BDIM * SDIM / 128);
        sgemm_nt<<<grid, 256>>>(rnn, fc_w, fc_b, out, BDIM * SDIM, IDIM, HDIM);
    }

    finalize_kernel<<<192, 256>>>(rnn, out);
}

// round 12
// speedup vs baseline: 1.9885x; 1.0511x over previous
#include <cuda_runtime.h>
#include <math.h>

#define BDIM 16
#define SDIM 2048
#define IDIM 1024
#define HDIM 1024
#define NBLK 128   // GRU persistent blocks (1 per SM, 8 hidden cols each)

// Scratch (static __device__ — runtime allocation is forbidden)
__device__ float g_gi[(size_t)BDIM * SDIM * 3 * HDIM];   // [B,S,3H]
__device__ float g_rnn[(size_t)BDIM * SDIM * HDIM];      // [B,S,H]
__device__ float g_hT[2 * HDIM * BDIM];                  // transposed h, double-buffered [buf][k][b]

// grid barrier state (self-resetting across graph replays)
__device__ unsigned g_count = 0;
__device__ volatile unsigned g_gen = 0;

// ---------------------------------------------------------------------------
// f32x2 packed-math helpers (sm_100+)
// ---------------------------------------------------------------------------
__device__ __forceinline__ unsigned long long dup2(float x) {
    unsigned long long r;
    asm("mov.b64 %0, {%1, %1};" : "=l"(r) : "f"(x));
    return r;
}
__device__ __forceinline__ float2 unpack2(unsigned long long v) {
    float2 f;
    asm("mov.b64 {%0, %1}, %2;" : "=f"(f.x), "=f"(f.y) : "l"(v));
    return f;
}
#define FMA2(d, a, b) asm("fma.rn.f32x2 %0, %1, %2, %0;" : "+l"(d) : "l"(a), "l"(b))
#define ADD2(d, a)    asm("add.rn.f32x2 %0, %0, %1;"     : "+l"(d) : "l"(a))

// ---------------------------------------------------------------------------
// NT SGEMM (f32x2), register double-buffered:
//   C[m,n] = sum_k A[m,k] * W[n,k] + bias[n]
// 128x128 tile, BK=16, 256 threads, 8x8 per thread (as 8x4 f32x2).
// Next tile's LDGs are issued BEFORE current tile's compute (held in regs),
// so the ~600cyc load latency hides under the ~1024cyc FMA block.
// ---------------------------------------------------------------------------
__global__ void __launch_bounds__(256, 2) sgemm_nt(
    const float* __restrict__ A, const float* __restrict__ W,
    const float* __restrict__ bias, float* __restrict__ C,
    int M, int N, int K)
{
    __shared__ float As[16][128];
    __shared__ float Bs[16][128];

    const int tid = threadIdx.x;
    const int bm = blockIdx.y * 128;
    const int bn = blockIdx.x * 128;
    const int tx = tid & 15;
    const int ty = tid >> 4;

    // load mapping: element e in [0,512): row = e>>2 (0..127), quad = e&3
    const int row0 = tid >> 2;          // 0..63   (e = tid)
    const int quad = tid & 3;           // row1 = row0 + 64 (e = tid + 256)

    const float* Aball0 = A + (size_t)(bm + row0) * K + quad * 4;
    const float* Aball1 = A + (size_t)(bm + row0 + 64) * K + quad * 4;
    const float* Wball0 = W + (size_t)(bn + row0) * K + quad * 4;
    const float* Wball1 = W + (size_t)(bn + row0 + 64) * K + quad * 4;

    unsigned long long acc[8][4];
#pragma unroll
    for (int i = 0; i < 8; i++)
#pragma unroll
        for (int j = 0; j < 4; j++) acc[i][j] = 0ull;

    // prologue: load tile 0 and store to smem
    {
        float4 av0 = *(const float4*)(Aball0);
        float4 av1 = *(const float4*)(Aball1);
        float4 wv0 = *(const float4*)(Wball0);
        float4 wv1 = *(const float4*)(Wball1);
        As[quad * 4 + 0][row0] = av0.x; As[quad * 4 + 1][row0] = av0.y;
        As[quad * 4 + 2][row0] = av0.z; As[quad * 4 + 3][row0] = av0.w;
        As[quad * 4 + 0][row0 + 64] = av1.x; As[quad * 4 + 1][row0 + 64] = av1.y;
        As[quad * 4 + 2][row0 + 64] = av1.z; As[quad * 4 + 3][row0 + 64] = av1.w;
        Bs[quad * 4 + 0][row0] = wv0.x; Bs[quad * 4 + 1][row0] = wv0.y;
        Bs[quad * 4 + 2][row0] = wv0.z; Bs[quad * 4 + 3][row0] = wv0.w;
        Bs[quad * 4 + 0][row0 + 64] = wv1.x; Bs[quad * 4 + 1][row0 + 64] = wv1.y;
        Bs[quad * 4 + 2][row0 + 64] = wv1.z; Bs[quad * 4 + 3][row0 + 64] = wv1.w;
    }
    __syncthreads();

    const int NT = K / 16;
    for (int kt = 0; kt < NT; kt++) {
        // prefetch next tile into registers (latency hidden by compute below)
        float4 av0, av1, wv0, wv1;
        const bool more = (kt + 1 < NT);
        if (more) {
            const int k0 = (kt + 1) * 16;
            av0 = *(const float4*)(Aball0 + k0);
            av1 = *(const float4*)(Aball1 + k0);
            wv0 = *(const float4*)(Wball0 + k0);
            wv1 = *(const float4*)(Wball1 + k0);
        }

        // compute current tile
#pragma unroll
        for (int k = 0; k < 16; k++) {
            float a8[8];
            *(float4*)&a8[0] = *(const float4*)&As[k][ty * 8];
            *(float4*)&a8[4] = *(const float4*)&As[k][ty * 8 + 4];
            unsigned long long bp[4];
            {
                ulonglong2 t0 = *(const ulonglong2*)&Bs[k][tx * 8];
                ulonglong2 t1 = *(const ulonglong2*)&Bs[k][tx * 8 + 4];
                bp[0] = t0.x; bp[1] = t0.y; bp[2] = t1.x; bp[3] = t1.y;
            }
            unsigned long long ad[8];
#pragma unroll
            for (int i = 0; i < 8; i++) ad[i] = dup2(a8[i]);
#pragma unroll
            for (int i = 0; i < 8; i++)
#pragma unroll
                for (int j = 0; j < 4; j++)
                    FMA2(acc[i][j], ad[i], bp[j]);
        }
        __syncthreads();   // smem fully consumed

        if (more) {
            As[quad * 4 + 0][row0] = av0.x; As[quad * 4 + 1][row0] = av0.y;
            As[quad * 4 + 2][row0] = av0.z; As[quad * 4 + 3][row0] = av0.w;
            As[quad * 4 + 0][row0 + 64] = av1.x; As[quad * 4 + 1][row0 + 64] = av1.y;
            As[quad * 4 + 2][row0 + 64] = av1.z; As[quad * 4 + 3][row0 + 64] = av1.w;
            Bs[quad * 4 + 0][row0] = wv0.x; Bs[quad * 4 + 1][row0] = wv0.y;
            Bs[quad * 4 + 2][row0] = wv0.z; Bs[quad * 4 + 3][row0] = wv0.w;
            Bs[quad * 4 + 0][row0 + 64] = wv1.x; Bs[quad * 4 + 1][row0 + 64] = wv1.y;
            Bs[quad * 4 + 2][row0 + 64] = wv1.z; Bs[quad * 4 + 3][row0 + 64] = wv1.w;
            __syncthreads();   // next tile visible
        }
    }

#pragma unroll
    for (int i = 0; i < 8; i++) {
        size_t row = (size_t)(bm + ty * 8 + i);
#pragma unroll
        for (int j = 0; j < 4; j++) {
            float2 f = unpack2(acc[i][j]);
            int n = bn + tx * 8 + 2 * j;
            float2 v;
            v.x = f.x + bias[n];
            v.y = f.y + bias[n + 1];
            *(float2*)&C[row * N + n] = v;
        }
    }
}

// ---------------------------------------------------------------------------
// Persistent GRU — EXACT R4 version (best measured: 21.05ms total).
// 128 blocks x 256 threads; block owns 8 hidden cols.
// ---------------------------------------------------------------------------
__device__ __forceinline__ void gsync() {
    __syncthreads();
    if (threadIdx.x == 0) {
        unsigned gen = g_gen;
        __threadfence();
        if (atomicAdd(&g_count, 1u) == NBLK - 1u) {
            g_count = 0;
            __threadfence();
            g_gen = gen + 1;
        } else {
            while (g_gen == gen) {}
            __threadfence();
        }
    }
    __syncthreads();
}

#define HROW 20            // floats per h_s row (16 used + 4 pad -> conflict-free LDS.128)
#define SM_W   (24 * 1024)                 // floats
#define SM_H   (1024 * HROW)               // floats
#define SM_RED 192                         // ull (f32x2) entries

__global__ void __launch_bounds__(256, 1) gru_persistent(
    const float* __restrict__ gi, const float* __restrict__ w_hh,
    const float* __restrict__ b_hh, float* __restrict__ rnn,
    float* __restrict__ hT)
{
    extern __shared__ float sm[];
    float* w_s = sm;
    float* h_s = sm + SM_W;
    unsigned long long* red_s = (unsigned long long*)(sm + SM_W + SM_H);

    const int tid = threadIdx.x;
    const int bx = blockIdx.x;
    const int cg = tid >> 6;      // 0..3 column group
    const int ks = tid & 63;      // k slice

    // --- load own w_hh rows into smem (once) ---
    for (int idx = tid; idx < 24 * 256; idx += 256) {
        int lr = idx >> 8;
        int k4 = idx & 255;
        int g = lr >> 3, jl = lr & 7;
        float4 v = *(const float4*)(w_hh + ((size_t)(g * 1024 + bx * 8 + jl)) * 1024 + k4 * 4);
        *(float4*)(w_s + lr * 1024 + k4 * 4) = v;
    }

    // combine-thread constants
    const int jl_c = tid >> 4, b_c = tid & 15;
    const int col_c = bx * 8 + jl_c;
    float bh0 = 0.f, bh1 = 0.f, bh2 = 0.f;
    if (tid < 128) {
        bh0 = b_hh[col_c];
        bh1 = b_hh[1024 + col_c];
        bh2 = b_hh[2048 + col_c];
    }

    // per-thread w pointers (invariant across steps): c = jsub*3 + g
    const int j0 = cg * 2;
    const float* wc[6];
#pragma unroll
    for (int jsub = 0; jsub < 2; jsub++)
#pragma unroll
        for (int g = 0; g < 3; g++)
            wc[jsub * 3 + g] = w_s + (g * 8 + j0 + jsub) * 1024 + ks;

    __syncthreads();

    for (int t = 0; t < SDIM; t++) {
        // --- stage h_{t-1} into h_s[k][b] ---
        if (t == 0) {
            float4 z4 = make_float4(0.f, 0.f, 0.f, 0.f);
            for (int r = tid; r < SM_H / 4; r += 256)
                ((float4*)h_s)[r] = z4;
        } else {
            const size_t hoff = (size_t)((t - 1) & 1) * (HDIM * BDIM);
            for (int r = tid; r < 4096; r += 256) {
                float4 v = *(const float4*)(hT + hoff + r * 4);
                int k = r >> 2, b4 = r & 3;
                *(float4*)(h_s + k * HROW + b4 * 4) = v;
            }
        }
        __syncthreads();

        // --- prefetch gi + hprev (hidden under the mainloop) ---
        float gir = 0.f, giz = 0.f, gin = 0.f, hprev = 0.f;
        if (tid < 128) {
            const size_t gb = ((size_t)b_c * SDIM + t) * 3072 + col_c;
            gir = __ldg(gi + gb);
            giz = __ldg(gi + gb + 1024);
            gin = __ldg(gi + gb + 2048);
            hprev = h_s[col_c * HROW + b_c];
        }

        // --- mainloop: 6 cols x 8 f32x2 x 16 k-iters ---
        unsigned long long acc[6][8];
#pragma unroll
        for (int c = 0; c < 6; c++)
#pragma unroll
            for (int p = 0; p < 8; p++) acc[c][p] = 0ull;

#pragma unroll 4
        for (int i = 0; i < 16; i++) {
            const int k = ks + (i << 6);
            const float* hrow = h_s + k * HROW;
            unsigned long long hp[8];
            {
                ulonglong2 u0 = *(const ulonglong2*)(hrow);
                ulonglong2 u1 = *(const ulonglong2*)(hrow + 4);
                ulonglong2 u2 = *(const ulonglong2*)(hrow + 8);
                ulonglong2 u3 = *(const ulonglong2*)(hrow + 12);
                hp[0] = u0.x; hp[1] = u0.y; hp[2] = u1.x; hp[3] = u1.y;
                hp[4] = u2.x; hp[5] = u2.y; hp[6] = u3.x; hp[7] = u3.y;
            }
#pragma unroll
            for (int c = 0; c < 6; c++) {
                unsigned long long wd = dup2(wc[c][i << 6]);
#pragma unroll
                for (int p = 0; p < 8; p++) FMA2(acc[c][p], wd, hp[p]);
            }
        }

        // --- 64-way k reduction in two halves (dump reuses h_s) ---
        unsigned long long* dmp = (unsigned long long*)h_s;
#pragma unroll
        for (int hh = 0; hh < 2; hh++) {
            __syncthreads();   // h_s / previous dump fully consumed
#pragma unroll
            for (int g = 0; g < 3; g++)
#pragma unroll
                for (int p = 0; p < 8; p++)
                    dmp[tid * 25 + g * 8 + p] = acc[hh * 3 + g][p];
            __syncthreads();
            if (tid < 96) {
                int cgo = tid / 24, s = tid % 24;
                unsigned long long sum = dmp[(cgo * 64) * 25 + s];
#pragma unroll 8
                for (int q = 1; q < 64; q++)
                    ADD2(sum, dmp[(cgo * 64 + q) * 25 + s]);
                red_s[hh * 96 + cgo * 24 + s] = sum;
            }
        }
        __syncthreads();

        // --- combine + activations + write ---
        if (tid < 128) {
            int cgc = jl_c >> 1, hh = jl_c & 1, p = b_c >> 1, lane = b_c & 1;
            const float* rf = (const float*)red_s;
            int base = (hh * 96 + cgc * 24) * 2 + p * 2 + lane;
            float ar = rf[base];
            float az = rf[base + 16];   // (g=1)*8*2
            float an = rf[base + 32];   // (g=2)*8*2

            float r = 1.f / (1.f + expf(-(gir + ar + bh0)));
            float z = 1.f / (1.f + expf(-(giz + az + bh1)));
            float n = tanhf(gin + r * (an + bh2));
            float hnew = (1.f - z) * n + z * hprev;

            rnn[((size_t)b_c * SDIM + t) * HDIM + col_c] = hnew;
            hT[(t & 1) * (HDIM * BDIM) + col_c * BDIM + b_c] = hnew;
        }

        gsync();   // h_T[t] visible chip-wide before anyone stages step t+1
    }
}

// ---------------------------------------------------------------------------
// hidden = rnn[:, S-1, :]; attn = ones (softmax over a size-1 axis).
// d_out layout: [output B*S*I][hidden B*H][attn B*S]
// ---------------------------------------------------------------------------
__global__ void finalize_kernel(const float* __restrict__ rnn, float* __restrict__ out)
{
    const size_t OUT_ELEMS = (size_t)BDIM * SDIM * IDIM;
    int i = blockIdx.x * blockDim.x + threadIdx.x;
    if (i < BDIM * HDIM) {
        int b = i >> 10, h = i & 1023;
        out[OUT_ELEMS + i] = rnn[((size_t)b * SDIM + (SDIM - 1)) * HDIM + h];
    }
    if (i < BDIM * SDIM) {
        out[OUT_ELEMS + BDIM * HDIM + i] = 1.0f;
    }
}

extern "C" void kernel_launch(void* const* d_in, const int* in_sizes, int n_in,
                              void* d_out, int out_size)
{
    const float* x    = (const float*)d_in[0];
    // d_in[1..4] = attn MLP -> algebraically dead (softmax over size-1 axis == 1)
    const float* w_ih = (const float*)d_in[5];
    const float* w_hh = (const float*)d_in[6];
    const float* b_ih = (const float*)d_in[7];
    const float* b_hh = (const float*)d_in[8];
    const float* fc_w = (const float*)d_in[9];
    const float* fc_b = (const float*)d_in[10];
    float* out = (float*)d_out;

    float *gi = nullptr, *rnn = nullptr, *hT = nullptr;
    cudaGetSymbolAddress((void**)&gi, g_gi);
    cudaGetSymbolAddress((void**)&rnn, g_rnn);
    cudaGetSymbolAddress((void**)&hT, g_hT);

    const int smemB = (SM_W + SM_H) * (int)sizeof(float) + SM_RED * (int)sizeof(unsigned long long);
    static bool attr_done = false;
    if (!attr_done) {
        cudaFuncSetAttribute(gru_persistent, cudaFuncAttributeMaxDynamicSharedMemorySize, smemB);
        attr_done = true;
    }

    // gi = x @ w_ih^T + b_ih   (M=32768, N=3072, K=1024)
    {
        dim3 grid(3 * HDIM / 128, BDIM * SDIM / 128);
        sgemm_nt<<<grid, 256>>>(x, w_ih, b_ih, gi, BDIM * SDIM, 3 * HDIM, IDIM);
    }

    // GRU: one persistent kernel, 2048 steps, software grid barrier
    gru_persistent<<<NBLK, 256, smemB>>>(gi, w_hh, b_hh, rnn, hT);

    // output = rnn_out @ fc_w^T + fc_b   (M=32768, N=1024, K=1024)
    {
        dim3 grid(IDIM / 128, BDIM * SDIM / 128);
        sgemm_nt<<<grid, 256>>>(rnn, fc_w, fc_b, out, BDIM * SDIM, IDIM, HDIM);
    }

    finalize_kernel<<<192, 256>>>(rnn, out);
}